// round 1
// baseline (speedup 1.0000x reference)
#include <cuda_runtime.h>

// Problem constants (fixed by the dataset)
#define L_WIN   10
#define D_EMB   100
#define V_POI   1000
#define V_HOUR  24
#define V_WD    7
#define NROWS   (V_POI + V_HOUR + V_WD)   // 1031 token rows
#define NCOLS   (V_POI + V_HOUR + V_WD)   // 1031 output columns
#define TLSTRIDE 1152                     // padded col stride (128B-aligned rows)

// Precomputed token-logit table: TL[row, n] = emb_attr(row) . W_head(n)[:, seg(attr)]
// rows: [0,1000) poi tokens, [1000,1024) hour tokens, [1024,1031) weekday tokens
// cols: [0,1000) poi logits, [1000,1024) hour logits, [1024,1031) weekday logits
// cols [1031,1152) are zero padding.
__device__ float g_TL[NROWS * TLSTRIDE];   // 4.75 MB scratch (static, allowed)

// ---------------------------------------------------------------------------
// Kernel 1: build the token-logit table. 212 MFLOP total -> trivial.
// Tile: 16 rows x 32 cols, K=100 contraction through shared memory.
// ---------------------------------------------------------------------------
__global__ void build_tl_kernel(const float* __restrict__ emb_poi,
                                const float* __restrict__ emb_hour,
                                const float* __restrict__ emb_wd,
                                const float* __restrict__ W_poi,
                                const float* __restrict__ W_hour,
                                const float* __restrict__ W_wd) {
    __shared__ float Ws[32][301];   // 301 stride: gcd(301%32=13,32)=1 -> conflict-free
    __shared__ float Es[16][100];

    const int n0  = blockIdx.x * 32;
    const int r0  = blockIdx.y * 16;
    const int tid = threadIdx.y * 32 + threadIdx.x;   // 512 threads

    // Load full 300-wide W rows for the 32 output columns of this tile
    for (int idx = tid; idx < 32 * 300; idx += 512) {
        int j = idx / 300, d = idx - j * 300;
        int n = n0 + j;
        float v = 0.f;
        if (n < V_POI)                  v = W_poi[n * 300 + d];
        else if (n < V_POI + V_HOUR)    v = W_hour[(n - V_POI) * 300 + d];
        else if (n < NCOLS)             v = W_wd[(n - V_POI - V_HOUR) * 300 + d];
        Ws[j][d] = v;
    }
    // Load 100-wide embedding rows for the 16 token rows of this tile
    for (int idx = tid; idx < 16 * 100; idx += 512) {
        int i = idx / 100, d = idx - i * 100;
        int r = r0 + i;
        float v = 0.f;
        if (r < V_POI)                  v = emb_poi[r * D_EMB + d];
        else if (r < V_POI + V_HOUR)    v = emb_hour[(r - V_POI) * D_EMB + d];
        else if (r < NROWS)             v = emb_wd[(r - V_POI - V_HOUR) * D_EMB + d];
        Es[i][d] = v;
    }
    __syncthreads();

    const int i = threadIdx.y;
    const int j = threadIdx.x;
    const int r = r0 + i;
    if (r >= NROWS) return;

    const int aoff = (r < V_POI) ? 0 : (r < V_POI + V_HOUR) ? D_EMB : 2 * D_EMB;
    float acc = 0.f;
#pragma unroll
    for (int d = 0; d < D_EMB; d++)
        acc += Es[i][d] * Ws[j][aoff + d];   // Es broadcast per warp; Ws conflict-free

    // cols >= NCOLS got zero W rows -> acc == 0 -> pad columns are zeroed
    g_TL[r * TLSTRIDE + n0 + j] = acc;
}

// ---------------------------------------------------------------------------
// Kernel 2: per-batch-row gather-sum over token rows of g_TL.
// One block per batch element, 256 threads, float4 column coverage:
//   group A: cols [4*tid, 4*tid+4)           (covers 0..1023)
//   group B: cols [1024+4*tid, ...) tid<32   (covers 1024..1151)
// ---------------------------------------------------------------------------
__device__ __forceinline__ void emit_col(float* __restrict__ out, int B, int b, int n,
                                         float sum, float inv,
                                         const float* __restrict__ b_poi,
                                         const float* __restrict__ b_hour,
                                         const float* __restrict__ b_wd) {
    if (n < V_POI) {
        out[(size_t)b * V_POI + n] = sum * inv + b_poi[n];
    } else if (n < V_POI + V_HOUR) {
        out[(size_t)B * V_POI + (size_t)b * V_HOUR + (n - V_POI)] =
            sum * inv + b_hour[n - V_POI];
    } else if (n < NCOLS) {
        out[(size_t)B * (V_POI + V_HOUR) + (size_t)b * V_WD + (n - V_POI - V_HOUR)] =
            sum * inv + b_wd[n - V_POI - V_HOUR];
    }
}

__global__ void cbow_gather_kernel(const int* __restrict__ x,
                                   const int* __restrict__ lens,
                                   const float* __restrict__ b_poi,
                                   const float* __restrict__ b_hour,
                                   const float* __restrict__ b_wd,
                                   float* __restrict__ out,
                                   int B) {
    __shared__ int   s_off[32];   // row offsets in float4 units
    __shared__ int   s_T;
    __shared__ float s_inv;

    const int b   = blockIdx.x;
    const int tid = threadIdx.x;

    if (tid < 30) {
        int l = tid / 3, a = tid - l * 3;                 // l-major, attr-minor
        int tok = x[(b * L_WIN + l) * 3 + a];
        int row = (a == 0) ? tok : ((a == 1) ? (V_POI + tok) : (V_POI + V_HOUR + tok));
        s_off[tid] = row * (TLSTRIDE / 4);
    }
    if (tid == 0) {
        int e = lens[b];
        e = min(max(e, 1), L_WIN);
        s_T   = e * 3;                                    // first e*3 entries = l<e, all attrs
        s_inv = 1.0f / (float)e;
    }
    __syncthreads();

    const int   T   = s_T;
    const float inv = s_inv;

    float4 a0 = make_float4(0.f, 0.f, 0.f, 0.f);
    float4 a1 = make_float4(0.f, 0.f, 0.f, 0.f);
    const bool two = (tid < 32);   // second column group (cols 1024..1151)

    const float4* __restrict__ TL4 = reinterpret_cast<const float4*>(g_TL);

    for (int t = 0; t < T; t++) {
        const float4* row = TL4 + s_off[t];
        float4 v = row[tid];
        a0.x += v.x; a0.y += v.y; a0.z += v.z; a0.w += v.w;
        if (two) {                       // warp 0 only -> no intra-warp divergence
            float4 w = row[256 + tid];
            a1.x += w.x; a1.y += w.y; a1.z += w.z; a1.w += w.w;
        }
    }

    const int n0 = tid * 4;
    emit_col(out, B, b, n0 + 0, a0.x, inv, b_poi, b_hour, b_wd);
    emit_col(out, B, b, n0 + 1, a0.y, inv, b_poi, b_hour, b_wd);
    emit_col(out, B, b, n0 + 2, a0.z, inv, b_poi, b_hour, b_wd);
    emit_col(out, B, b, n0 + 3, a0.w, inv, b_poi, b_hour, b_wd);
    if (two) {
        const int n1 = 1024 + tid * 4;
        emit_col(out, B, b, n1 + 0, a1.x, inv, b_poi, b_hour, b_wd);
        emit_col(out, B, b, n1 + 1, a1.y, inv, b_poi, b_hour, b_wd);
        emit_col(out, B, b, n1 + 2, a1.z, inv, b_poi, b_hour, b_wd);
        emit_col(out, B, b, n1 + 3, a1.w, inv, b_poi, b_hour, b_wd);
    }
}

// ---------------------------------------------------------------------------
// Launch
// ---------------------------------------------------------------------------
extern "C" void kernel_launch(void* const* d_in, const int* in_sizes, int n_in,
                              void* d_out, int out_size) {
    const int*   x        = (const int*)  d_in[0];
    const int*   lens     = (const int*)  d_in[1];
    const float* emb_poi  = (const float*)d_in[2];
    const float* emb_hour = (const float*)d_in[3];
    const float* emb_wd   = (const float*)d_in[4];
    const float* W_poi    = (const float*)d_in[5];
    const float* b_poi    = (const float*)d_in[6];
    const float* W_hour   = (const float*)d_in[7];
    const float* b_hour   = (const float*)d_in[8];
    const float* W_wd     = (const float*)d_in[9];
    const float* b_wd     = (const float*)d_in[10];

    const int B = in_sizes[0] / (L_WIN * 3);

    dim3 g1(TLSTRIDE / 32, (NROWS + 15) / 16);   // 36 x 65 tiles
    build_tl_kernel<<<g1, dim3(32, 16)>>>(emb_poi, emb_hour, emb_wd,
                                          W_poi, W_hour, W_wd);

    cbow_gather_kernel<<<B, 256>>>(x, lens, b_poi, b_hour, b_wd,
                                   (float*)d_out, B);
}